// round 9
// baseline (speedup 1.0000x reference)
#include <cuda_runtime.h>
#include <math.h>

// NUFFT layer — fully analytic (round-8 math), round-9 structure:
// one cluster of 8 CTAs per batch; cluster barrier replaces the grid-wide
// barrier (144-CTA rendezvous = dispatch-skew floor; 8-CTA HW barrier isn't).
//   Phase A (per CTA): mode partials over its 128 particles.
//   cluster.sync; reduce 8 partials; U/V tables; edge field; direct output
//   with clamp-vs-periodization wrap corrections.

#define NMODES 112          // modes >= 106 underflow to exactly 0 (as reference fp32)
#define NBATCH 8
#define NPART  1024
#define CLUST  8
#define GRIDB  (NBATCH * CLUST)   // 64
#define TPB    512

__device__ float g_part[NBATCH][2 * NMODES][CLUST];   // [b][A|B x mode][rank]

#define TWO_PI_F 6.2831853071795864769f

__device__ __forceinline__ float frac_mx(float m, float x)
{   // frac(m*x) in ~[-0.5,0.5]; exact Dekker split (m <= 104 < 2^7, x fp32)
    float hi = m * x;
    float lo = fmaf(m, x, -hi);
    return (hi - rintf(hi)) + lo;
}

__global__ __launch_bounds__(TPB, 1) __cluster_dims__(CLUST, 1, 1)
void k_fused(
    const float* __restrict__ x,
    const float* __restrict__ sigma_var,
    const float* __restrict__ shift0,
    const float* __restrict__ shift1,
    const float* __restrict__ amp0,
    const float* __restrict__ amp1,
    float* __restrict__ out)
{
    const int b    = blockIdx.x >> 3;     // batch
    const int rank = blockIdx.x & 7;      // rank within cluster
    const int tid  = threadIdx.x;
    const int w    = tid >> 5;
    const int lane = tid & 31;

    __shared__ float4 tabU[NMODES];       // (A, B, U0, U1)  no-deconv multipliers
    __shared__ float2 tabV[NMODES];       // (V0, V1)        with-deconv (edge f)
    __shared__ float  sf0[12], sf1[12];   // f at grid pts {0..5, 1995..2000}

    // ---------------- Phase A: mode partials for this CTA's 128 particles
    // Warps 0..13: 8 modes each, v[16] accumulators, 4 particles per lane.
    if (w < 14) {
        float v[16];
#pragma unroll
        for (int k = 0; k < 16; ++k) v[k] = 0.f;

#pragma unroll
        for (int pp = 0; pp < 4; ++pp) {
            const float xv = x[b * NPART + rank * 128 + pp * 32 + lane];
            float sw_, cw_;                           // step e^{2*pi*i*x}
            __sincosf(TWO_PI_F * (xv - rintf(xv)), &sw_, &cw_);
            float zr, zi;
            if (w == 0) { zr = 1.f; zi = 0.f; }
            else        { __sincosf(TWO_PI_F * frac_mx((float)(8 * w), xv), &zi, &zr); }
#pragma unroll
            for (int j = 0; j < 8; ++j) {
                v[2 * j]     += zr;
                v[2 * j + 1] += zi;
                float nzr = fmaf(zr, cw_, -zi * sw_);
                float nzi = fmaf(zi, cw_,  zr * sw_);
                zr = nzr; zi = nzi;
            }
        }
#pragma unroll
        for (int s = 0; s < 4; ++s) {                 // 15-shfl halving reduction
            const int  half = 8 >> s;
            const bool up   = (lane >> s) & 1;
#pragma unroll
            for (int k = 0; k < half; ++k) {
                float send = up ? v[k] : v[k + half];
                float recv = __shfl_xor_sync(0xffffffffu, send, 1 << s);
                v[k] = (up ? v[k + half] : v[k]) + recv;
            }
        }
        v[0] += __shfl_xor_sync(0xffffffffu, v[0], 16);
        if (lane < 16) {
            const int r = __brev(lane) >> 28;         // bitrev4 -> accumulator idx
            const int m = 8 * w + (r >> 1);
            g_part[b][(r & 1) * NMODES + m][rank] = v[0];
        }
    }

    // -------- cluster rendezvous (8 CTAs; HW barrier, stateless) ---------
    __threadfence();                                   // partials -> L2 visible
    asm volatile("barrier.cluster.arrive.aligned;" ::: "memory");
    asm volatile("barrier.cluster.wait.aligned;"   ::: "memory");

    // ---------------- reduce 8 rank-partials + spectral tables -----------
    if (tid < NMODES) {
        const int m = tid;
        float4 a0 = __ldcg((const float4*)&g_part[b][m][0]);
        float4 a1 = __ldcg((const float4*)&g_part[b][m][4]);
        float4 b0 = __ldcg((const float4*)&g_part[b][NMODES + m][0]);
        float4 b1 = __ldcg((const float4*)&g_part[b][NMODES + m][4]);
        float A = ((a0.x + a0.y) + (a0.z + a0.w)) + ((a1.x + a1.y) + (a1.z + a1.w));
        float B = ((b0.x + b0.y) + (b0.z + b0.w)) + ((b1.x + b1.y) + (b1.z + b1.w));

        const double TWO_PI_D = 6.283185307179586476925286766559;
        const double taud  = 12.0 / ((TWO_PI_D * 2001.0) * (TWO_PI_D * 2001.0));
        const float TAUF     = (float)taud;
        const float SQPIOTAU = (float)sqrt(3.14159265358979323846 / taud);
        const float s_   = sigma_var[0];
        const float q0   = 25.f * shift0[0] * shift0[0];
        const float q1   = 25.f * shift1[0] * shift1[0];
        const float FOURPI = 12.566370614359172f;
        float kk = TWO_PI_F * (float)m;
        float K2 = kk * kk;
        float fold = (m == 0) ? 1.f : 2.f;
        float base0 = fold * (-amp0[0]) * FOURPI / (K2 + q0);
        float inv  = 1.f / (K2 + q1);
        float base1 = fold * amp1[0] * FOURPI * inv * inv;
        float eg = __expf(-0.5f * s_ * s_ * K2);      // 0 for m >= ~106 (as ref)
        float eU = TWO_PI_F * eg;                     // window x deconv = 2*pi exactly
        float eV = SQPIOTAU * __expf((TAUF - 0.5f * s_ * s_) * K2);
        tabU[m] = make_float4(A, B, base0 * eU, base1 * eU);
        tabV[m] = make_float2(base0 * eV, base1 * eV);
    }
    __syncthreads();

    // ---------------- edge field: f (with deconv) at {0..5, 1995..2000} --
    if (tid < 64) {
        const int e = tid >> 2;                       // 0..15 (12 used)
        const int q = tid & 3;
        const int g = (e < 6) ? e : (1995 + (e - 6));

        const float C_HI = (float)(1.0 / 2001.0);
        const float C_LO = (float)(1.0 / 2001.0 - (double)((float)(1.0 / 2001.0)));
        const float gf     = (float)g;
        const float phi_hi = gf * C_HI;
        const float phi_lo = fmaf(gf, C_HI, -phi_hi) + gf * C_LO;

        float sw_, cw_;
        __sincosf(TWO_PI_F * ((phi_hi - rintf(phi_hi)) + phi_lo), &sw_, &cw_);
        float zr, zi;
        if (q == 0) { zr = 1.f; zi = 0.f; }
        else {
            float m0f = (float)(28 * q);
            float hi2 = m0f * phi_hi;
            float lo2 = fmaf(m0f, phi_hi, -hi2);
            float f   = (hi2 - rintf(hi2)) + (lo2 + m0f * phi_lo);
            __sincosf(TWO_PI_F * (f - rintf(f)), &zi, &zr);
        }
        float acc0 = 0.f, acc1 = 0.f;
#pragma unroll
        for (int j = 0; j < 28; ++j) {
            const int m = 28 * q + j;
            float4 t4 = tabU[m];                      // A, B
            float2 v2 = tabV[m];                      // V0, V1
            float tt = fmaf(t4.x, zr, t4.y * zi);
            acc0 = fmaf(v2.x, tt, acc0);
            acc1 = fmaf(v2.y, tt, acc1);
            float nzr = fmaf(zr, cw_, -zi * sw_);
            float nzi = fmaf(zi, cw_,  zr * sw_);
            zr = nzr; zi = nzi;
        }
        acc0 += __shfl_xor_sync(0xffffffffu, acc0, 1);
        acc0 += __shfl_xor_sync(0xffffffffu, acc0, 2);
        acc1 += __shfl_xor_sync(0xffffffffu, acc1, 1);
        acc1 += __shfl_xor_sync(0xffffffffu, acc1, 2);
        if (q == 0 && e < 12) { sf0[e] = acc0; sf1[e] = acc1; }
    }
    __syncthreads();

    // ---------------- main: 4 threads/particle, 28-mode chains -----------
    {
        const int s  = tid >> 2;                      // 0..127
        const int q  = tid & 3;
        const int p  = b * NPART + rank * 128 + s;
        const float xv = x[p];

        float sw_, cw_;                               // step e^{2*pi*i*x}
        __sincosf(TWO_PI_F * (xv - rintf(xv)), &sw_, &cw_);
        float zr, zi;                                 // base at m0 = 28q (exact)
        if (q == 0) { zr = 1.f; zi = 0.f; }
        else        { __sincosf(TWO_PI_F * frac_mx((float)(28 * q), xv), &zi, &zr); }

        float acc0 = 0.f, acc1 = 0.f;
#pragma unroll
        for (int j = 0; j < 28; ++j) {
            float4 t4 = tabU[28 * q + j];
            float tt = fmaf(t4.x, zr, t4.y * zi);
            acc0 = fmaf(t4.z, tt, acc0);
            acc1 = fmaf(t4.w, tt, acc1);
            float nzr = fmaf(zr, cw_, -zi * sw_);
            float nzi = fmaf(zi, cw_,  zr * sw_);
            zr = nzr; zi = nzi;
        }
        acc0 += __shfl_xor_sync(0xffffffffu, acc0, 1);
        acc0 += __shfl_xor_sync(0xffffffffu, acc0, 2);
        acc1 += __shfl_xor_sync(0xffffffffu, acc1, 1);
        acc1 += __shfl_xor_sync(0xffffffffu, acc1, 2);

        if (q == 0) {
            // wrap corrections (reference clamps; Poisson periodizes)
            const double TWO_PI_D = 6.283185307179586476925286766559;
            const float TAUF    = (float)(12.0 / ((TWO_PI_D * 2001.0) * (TWO_PI_D * 2001.0)));
            const float inv4tau = 1.f / (4.f * TAUF);
            const float invN    = (float)(1.0 / 2001.0);
            const int m0 = __float2int_rn(xv * 2001.0f);
            if (m0 <= 6) {
#pragma unroll
                for (int j = 1; j <= 6; ++j) {        // phantom n = -j -> grid 2001-j
                    float d = xv + (float)j * invN;
                    float wgt = invN * __expf(-d * d * inv4tau);
                    acc0 -= wgt * sf0[12 - j];
                    acc1 -= wgt * sf1[12 - j];
                }
            }
            if (m0 >= 1994) {
#pragma unroll
                for (int j = 0; j <= 5; ++j) {        // phantom n = 2001+j -> grid j
                    float d = xv - 1.f - (float)j * invN;
                    float wgt = invN * __expf(-d * d * inv4tau);
                    acc0 -= wgt * sf0[j];
                    acc1 -= wgt * sf1[j];
                }
            }
            out[2 * p]     = acc0;
            out[2 * p + 1] = acc1;
        }
    }
}

// ---------------------------------------------------------------------------
extern "C" void kernel_launch(void* const* d_in, const int* in_sizes, int n_in,
                              void* d_out, int out_size)
{
    (void)in_sizes; (void)n_in; (void)out_size;
    k_fused<<<GRIDB, TPB>>>((const float*)d_in[0], (const float*)d_in[1],
                            (const float*)d_in[2], (const float*)d_in[3],
                            (const float*)d_in[4], (const float*)d_in[5],
                            (float*)d_out);
}